// round 1
// baseline (speedup 1.0000x reference)
#include <cuda_runtime.h>

#define NN 8192
#define FI 128
#define FO 64
#define LRALPHA 0.2f
#define JS 4          // j-dimension splits
#define BJ 32         // j tile per smem stage
#define ITILE 64      // rows per block
#define RPW 8         // rows per warp

// ---- scratch (device globals: allocation-free) ----
__device__ float g_h [NN*FO];
__device__ float g_gp[NN*FO];   // exp(t_j)      * h_j
__device__ float g_gn[NN*FO];   // exp(a*t_j)    * h_j
__device__ float g_t[NN], g_u[NN], g_v[NN];
__device__ float g_s[NN], g_p[NN], g_q[NN];
__device__ float g_accP[JS][NN*FO];
__device__ float g_accN[JS][NN*FO];
__device__ float g_rsP[JS][NN];
__device__ float g_rsN[JS][NN];

// ---------------- kernel 1: h = x @ W ----------------
__global__ void k_gemm_h(const float* __restrict__ x, const float* __restrict__ W) {
    __shared__ float sW[FI*FO];     // 32KB
    __shared__ float sx[64][FI];    // 32KB
    int tid = threadIdx.x;
    for (int i = tid; i < FI*FO; i += 256) sW[i] = W[i];
    int r0 = blockIdx.x * 64;
    for (int i = tid; i < 64*FI; i += 256)
        sx[i >> 7][i & 127] = x[(size_t)(r0 + (i >> 7))*FI + (i & 127)];
    __syncthreads();
    int col = tid & 63;
    for (int rr = tid >> 6; rr < 64; rr += 4) {
        float acc = 0.f;
        #pragma unroll
        for (int k = 0; k < FI; k++) acc += sx[rr][k] * sW[k*FO + col];
        g_h[(size_t)(r0 + rr)*FO + col] = acc;
    }
}

// ------ kernel 2: per-row scalars s,t,p,q,u,v and scaled tables gp,gn ------
__global__ void k_scalars(const float* __restrict__ a) {
    int gwarp = (blockIdx.x * blockDim.x + threadIdx.x) >> 5;
    int lane  = threadIdx.x & 31;
    if (gwarp >= NN) return;
    float h0 = g_h[(size_t)gwarp*FO + lane];
    float h1 = g_h[(size_t)gwarp*FO + 32 + lane];
    float s = h0 * a[lane]      + h1 * a[lane + 32];
    float t = h0 * a[lane + 64] + h1 * a[lane + 96];
    #pragma unroll
    for (int o = 16; o; o >>= 1) {
        s += __shfl_xor_sync(0xffffffffu, s, o);
        t += __shfl_xor_sync(0xffffffffu, t, o);
    }
    float u = __expf(t), v = __expf(LRALPHA * t);
    if (lane == 0) {
        g_s[gwarp] = s; g_t[gwarp] = t;
        g_u[gwarp] = u; g_v[gwarp] = v;
        g_p[gwarp] = __expf(s); g_q[gwarp] = __expf(LRALPHA * s);
    }
    g_gp[(size_t)gwarp*FO + lane]      = u * h0;
    g_gp[(size_t)gwarp*FO + 32 + lane] = u * h1;
    g_gn[(size_t)gwarp*FO + lane]      = v * h0;
    g_gn[(size_t)gwarp*FO + 32 + lane] = v * h1;
}

// ---------------- kernel 3: masked branch-factorized accumulation ----------------
// warp handles RPW rows; lanes cover 64 cols (2 each). Sparse visit via ballot+ffs.
__global__ __launch_bounds__(256, 2) void k_main(const int* __restrict__ adj) {
    __shared__ float s_gp[BJ][FO];   // 8KB
    __shared__ float s_gn[BJ][FO];   // 8KB
    __shared__ float s_t[BJ], s_u[BJ], s_v[BJ];

    int warp = threadIdx.x >> 5, lane = threadIdx.x & 31;
    int i0 = blockIdx.x * ITILE + warp * RPW;
    int jb = blockIdx.y * (NN / JS);
    int je = jb + (NN / JS);

    float accP[RPW][2], accN[RPW][2], rsP[RPW], rsN[RPW], sRow[RPW];
    #pragma unroll
    for (int r = 0; r < RPW; r++) {
        accP[r][0] = accP[r][1] = accN[r][0] = accN[r][1] = 0.f;
        rsP[r] = rsN[r] = 0.f;
        sRow[r] = g_s[i0 + r];
    }

    for (int j0 = jb; j0 < je; j0 += BJ) {
        __syncthreads();
        for (int idx = threadIdx.x; idx < BJ * FO; idx += 256) {
            int jj = idx >> 6, c = idx & 63;
            s_gp[jj][c] = g_gp[(size_t)(j0 + jj)*FO + c];
            s_gn[jj][c] = g_gn[(size_t)(j0 + jj)*FO + c];
        }
        if (threadIdx.x < BJ) {
            s_t[threadIdx.x] = g_t[j0 + threadIdx.x];
            s_u[threadIdx.x] = g_u[j0 + threadIdx.x];
            s_v[threadIdx.x] = g_v[j0 + threadIdx.x];
        }
        __syncthreads();

        float tj = s_t[lane];
        int c0 = 2 * lane;
        #pragma unroll
        for (int r = 0; r < RPW; r++) {
            int av = adj[(size_t)(i0 + r)*NN + j0 + lane];   // coalesced 128B
            unsigned m = __ballot_sync(0xffffffffu, av > 0);
            unsigned c = __ballot_sync(0xffffffffu, tj + sRow[r] > 0.f);
            unsigned mp = m & c;
            unsigned mn = m & ~c;
            while (mp) {
                int jj = __ffs(mp) - 1; mp &= mp - 1;
                accP[r][0] += s_gp[jj][c0];
                accP[r][1] += s_gp[jj][c0 + 1];
                rsP[r]     += s_u[jj];
            }
            while (mn) {
                int jj = __ffs(mn) - 1; mn &= mn - 1;
                accN[r][0] += s_gn[jj][c0];
                accN[r][1] += s_gn[jj][c0 + 1];
                rsN[r]     += s_v[jj];
            }
        }
    }

    int sp = blockIdx.y;
    #pragma unroll
    for (int r = 0; r < RPW; r++) {
        size_t o = (size_t)(i0 + r)*FO + 2*lane;
        g_accP[sp][o]     = accP[r][0];
        g_accP[sp][o + 1] = accP[r][1];
        g_accN[sp][o]     = accN[r][0];
        g_accN[sp][o + 1] = accN[r][1];
        if (lane == 0) { g_rsP[sp][i0 + r] = rsP[r]; g_rsN[sp][i0 + r] = rsN[r]; }
    }
}

// ---------------- kernel 4: combine splits, scale, divide, ELU ----------------
__global__ void k_final(float* __restrict__ out) {
    int idx = blockIdx.x * 256 + threadIdx.x;      // over NN*FO
    int i = idx >> 6;
    float p = g_p[i], q = g_q[i];
    float num = 0.f, denP = 0.f, denN = 0.f;
    #pragma unroll
    for (int s2 = 0; s2 < JS; s2++) {
        num  += p * g_accP[s2][idx] + q * g_accN[s2][idx];
        denP += g_rsP[s2][i];
        denN += g_rsN[s2][i];
    }
    float hp = num / (p * denP + q * denN);
    out[idx] = hp > 0.f ? hp : expm1f(hp);
}

extern "C" void kernel_launch(void* const* d_in, const int* in_sizes, int n_in,
                              void* d_out, int out_size) {
    const float* x   = (const float*)d_in[0];
    const int*   adj = (const int*)  d_in[1];
    const float* W   = (const float*)d_in[2];
    const float* a   = (const float*)d_in[3];
    float* out = (float*)d_out;

    k_gemm_h<<<NN/64, 256>>>(x, W);
    k_scalars<<<NN/8, 256>>>(a);
    dim3 g3(NN / ITILE, JS);
    k_main<<<g3, 256>>>(adj);
    k_final<<<(NN*FO)/256, 256>>>(out);
}

// round 4
// speedup vs baseline: 1.2626x; 1.2626x over previous
#include <cuda_runtime.h>
#include <cuda_bf16.h>
#include <cstdint>

#define NN 8192
#define FI 128
#define FO 64
#define LRALPHA 0.2f
#define KSPLIT 2
#define MT 128          // M rows per CTA
#define KT 64           // j per K-tile
#define NB 72           // padded N (64 feat + 1 den + 7 pad)
#define NBLK (NB/8)     // 9 n8 blocks
#define STRIDE_OUT 72

// ---------------- device scratch ----------------
__device__ float g_h[NN*FO];
__device__ __align__(16) float g_t[NN];
__device__ float g_s[NN], g_p[NN], g_q[NN];
__device__ __align__(16) __nv_bfloat16 g_Bph[(size_t)NB*NN], g_Bpl[(size_t)NB*NN];
__device__ __align__(16) __nv_bfloat16 g_Bnh[(size_t)NB*NN], g_Bnl[(size_t)NB*NN];
__device__ float g_numP[KSPLIT][(size_t)NN*STRIDE_OUT];
__device__ float g_numN[KSPLIT][(size_t)NN*STRIDE_OUT];

// ---------------- helpers ----------------
__device__ __forceinline__ uint32_t smem_u32(const void* p) {
    uint32_t a;
    asm("{ .reg .u64 t; cvta.to.shared.u64 t, %1; cvt.u32.u64 %0, t; }" : "=r"(a) : "l"(p));
    return a;
}
#define SWZ(x) ((uint32_t)(x) ^ ((((uint32_t)(x)) >> 3) & 0x70u))

__device__ __forceinline__ void ldm_x4(uint32_t addr, uint32_t r[4]) {
    asm volatile("ldmatrix.sync.aligned.m8n8.x4.shared.b16 {%0,%1,%2,%3}, [%4];"
        : "=r"(r[0]), "=r"(r[1]), "=r"(r[2]), "=r"(r[3]) : "r"(addr));
}
__device__ __forceinline__ void ldm_x2(uint32_t addr, uint32_t r[2]) {
    asm volatile("ldmatrix.sync.aligned.m8n8.x2.shared.b16 {%0,%1}, [%2];"
        : "=r"(r[0]), "=r"(r[1]) : "r"(addr));
}
__device__ __forceinline__ void mma16816(float* c, const uint32_t* a, const uint32_t* b) {
    asm volatile("mma.sync.aligned.m16n8k16.row.col.f32.bf16.bf16.f32 "
        "{%0,%1,%2,%3}, {%4,%5,%6,%7}, {%8,%9}, {%0,%1,%2,%3};"
        : "+f"(c[0]), "+f"(c[1]), "+f"(c[2]), "+f"(c[3])
        : "r"(a[0]), "r"(a[1]), "r"(a[2]), "r"(a[3]), "r"(b[0]), "r"(b[1]));
}

// ---------------- kernel 1: h = x @ W ----------------
__global__ void k_gemm_h(const float* __restrict__ x, const float* __restrict__ W) {
    __shared__ float sW[FI*FO];
    __shared__ float sx[64][FI];
    int tid = threadIdx.x;
    for (int i = tid; i < FI*FO; i += 256) sW[i] = W[i];
    int r0 = blockIdx.x * 64;
    for (int i = tid; i < 64*FI; i += 256)
        sx[i >> 7][i & 127] = x[(size_t)(r0 + (i >> 7))*FI + (i & 127)];
    __syncthreads();
    int col = tid & 63;
    for (int rr = tid >> 6; rr < 64; rr += 4) {
        float acc = 0.f;
        #pragma unroll
        for (int k = 0; k < FI; k++) acc += sx[rr][k] * sW[k*FO + col];
        g_h[(size_t)(r0 + rr)*FO + col] = acc;
    }
}

// -------- kernel 2: per-row scalars s,t,p,q --------
__global__ void k_scalars(const float* __restrict__ a) {
    int gwarp = (blockIdx.x * blockDim.x + threadIdx.x) >> 5;
    int lane  = threadIdx.x & 31;
    if (gwarp >= NN) return;
    float h0 = g_h[(size_t)gwarp*FO + lane];
    float h1 = g_h[(size_t)gwarp*FO + 32 + lane];
    float s = h0 * a[lane]      + h1 * a[lane + 32];
    float t = h0 * a[lane + 64] + h1 * a[lane + 96];
    #pragma unroll
    for (int o = 16; o; o >>= 1) {
        s += __shfl_xor_sync(0xffffffffu, s, o);
        t += __shfl_xor_sync(0xffffffffu, t, o);
    }
    if (lane == 0) {
        g_s[gwarp] = s; g_t[gwarp] = t;
        g_p[gwarp] = __expf(s); g_q[gwarp] = __expf(LRALPHA * s);
    }
}

// -------- kernel 3: bf16 hi/lo value tables, N-major [n][j] --------
__global__ void k_tables() {
    int n = blockIdx.y;                         // 0..NB-1
    int j = blockIdx.x * 256 + threadIdx.x;     // 0..NN-1
    float t = g_t[j];
    float u = __expf(t), v = __expf(LRALPHA * t);
    float vp, vn;
    if (n < FO)      { float h = g_h[(size_t)j*FO + n]; vp = u * h; vn = v * h; }
    else if (n == FO){ vp = u; vn = v; }
    else             { vp = 0.f; vn = 0.f; }
    __nv_bfloat16 ph = __float2bfloat16(vp);
    __nv_bfloat16 pl = __float2bfloat16(vp - __bfloat162float(ph));
    __nv_bfloat16 nh = __float2bfloat16(vn);
    __nv_bfloat16 nl = __float2bfloat16(vn - __bfloat162float(nh));
    size_t o = (size_t)n*NN + j;
    g_Bph[o] = ph; g_Bpl[o] = pl; g_Bnh[o] = nh; g_Bnl[o] = nl;
}

// ---------------- kernel 4: HMMA masked GEMM ----------------
// SMEM layout (dynamic):
#define SM_SS   0                          // 128 floats = 512B
#define SM_AP   1024
#define A_BYTES (MT*128)                   // 16384 (128 rows x 64 bf16, stride 128B)
#define SM_AN   (SM_AP + A_BYTES)
#define SM_B    (SM_AN + A_BYTES)
#define B_BYTES (NB*128)                   // 9216
#define SM_TOTAL (SM_B + 4*B_BYTES)        // 70656

__global__ void __launch_bounds__(128) k_main_tc(const int* __restrict__ adj) {
    extern __shared__ char smem[];
    uint32_t sb = smem_u32(smem);
    int tid = threadIdx.x, w = tid >> 5, lane = tid & 31;
    int i0 = blockIdx.x * MT;
    int sp = blockIdx.y;
    int jbase = sp * (NN / KSPLIT);
    const int nTiles = (NN / KSPLIT) / KT;   // 64

    float* s_s = (float*)(smem + SM_SS);
    if (tid < MT) s_s[tid] = g_s[i0 + tid];

    float accP[2][NBLK][4], accN[2][NBLK][4];
    #pragma unroll
    for (int mt = 0; mt < 2; mt++)
        #pragma unroll
        for (int nb = 0; nb < NBLK; nb++)
            #pragma unroll
            for (int e = 0; e < 4; e++) { accP[mt][nb][e] = 0.f; accN[mt][nb][e] = 0.f; }

    // per-lane address pieces (k loop invariant)
    uint32_t aRowByte = (uint32_t)(w * 32 + (lane & 15)) * 128;      // + mt*2048
    uint32_t aKHalf   = ((lane >> 4) & 1) * 16;                      // bytes
    uint32_t bNByte   = (uint32_t)(lane & 7) * 128;                  // + nb*1024
    uint32_t bKHalf   = ((lane >> 3) & 1) * 16;                      // bytes

    for (int t = 0; t < nTiles; t++) {
        int j0 = jbase + t * KT;
        __syncthreads();   // prev tile's ldmatrix reads done before overwrite

        // ---- build bf16 mask tiles A_P, A_N (128 x 64, SW128) ----
        #pragma unroll
        for (int it = 0; it < 16; it++) {
            int idx = it * 128 + tid;     // 0..2047
            int r = idx >> 4, seg = idx & 15;
            int4 av = *(const int4*)(adj + (size_t)(i0 + r) * NN + j0 + seg * 4);
            float4 t4 = *(const float4*)(g_t + j0 + seg * 4);
            float sr = s_s[r];
            bool m0 = av.x > 0, m1 = av.y > 0, m2 = av.z > 0, m3 = av.w > 0;
            bool c0 = sr + t4.x > 0.f, c1 = sr + t4.y > 0.f;
            bool c2 = sr + t4.z > 0.f, c3 = sr + t4.w > 0.f;
            uint32_t p01 = ((m0 && c0) ? 0x3F80u : 0u) | ((m1 && c1) ? 0x3F800000u : 0u);
            uint32_t p23 = ((m2 && c2) ? 0x3F80u : 0u) | ((m3 && c3) ? 0x3F800000u : 0u);
            uint32_t n01 = ((m0 && !c0) ? 0x3F80u : 0u) | ((m1 && !c1) ? 0x3F800000u : 0u);
            uint32_t n23 = ((m2 && !c2) ? 0x3F80u : 0u) | ((m3 && !c3) ? 0x3F800000u : 0u);
            uint32_t boff = SWZ((uint32_t)(r * 128 + seg * 8));
            *(uint2*)(smem + SM_AP + boff) = make_uint2(p01, p23);
            *(uint2*)(smem + SM_AN + boff) = make_uint2(n01, n23);
        }
        // ---- stage B tiles (4 streams, NB x 64 bf16, SW128) ----
        {
            const __nv_bfloat16* srcs[4] = {g_Bph, g_Bpl, g_Bnh, g_Bnl};
            #pragma unroll
            for (int st = 0; st < 4; st++) {
                const __nv_bfloat16* s = srcs[st];
                char* dst = smem + SM_B + st * B_BYTES;
                for (int v = tid; v < NB * 8; v += 128) {
                    int n = v >> 3, ch = v & 7;
                    uint32_t boff = SWZ((uint32_t)(n * 128 + ch * 16));
                    *(uint4*)(dst + boff) = *(const uint4*)(s + (size_t)n * NN + j0 + ch * 8);
                }
            }
        }
        __syncthreads();

        // ---- MMA phase: 4 ksteps of k16 ----
        #pragma unroll
        for (int ks = 0; ks < 4; ks++) {
            uint32_t kByteA = (uint32_t)ks * 32 + aKHalf;
            uint32_t kByteB = (uint32_t)ks * 32 + bKHalf;
            uint32_t aP[2][4], aN[2][4];
            #pragma unroll
            for (int mt = 0; mt < 2; mt++) {
                uint32_t off = SWZ(aRowByte + mt * 2048u + kByteA);
                ldm_x4(sb + SM_AP + off, aP[mt]);
                ldm_x4(sb + SM_AN + off, aN[mt]);
            }
            #pragma unroll
            for (int nb = 0; nb < NBLK; nb++) {
                uint32_t boff = SWZ(bNByte + nb * 1024u + kByteB);
                uint32_t b[2];
                ldm_x2(sb + SM_B + 0 * B_BYTES + boff, b);          // P hi
                mma16816(accP[0][nb], aP[0], b);
                mma16816(accP[1][nb], aP[1], b);
                ldm_x2(sb + SM_B + 1 * B_BYTES + boff, b);          // P lo
                mma16816(accP[0][nb], aP[0], b);
                mma16816(accP[1][nb], aP[1], b);
                ldm_x2(sb + SM_B + 2 * B_BYTES + boff, b);          // N hi
                mma16816(accN[0][nb], aN[0], b);
                mma16816(accN[1][nb], aN[1], b);
                ldm_x2(sb + SM_B + 3 * B_BYTES + boff, b);          // N lo
                mma16816(accN[0][nb], aN[0], b);
                mma16816(accN[1][nb], aN[1], b);
            }
        }
    }

    // ---- epilogue: write fp32 partials ----
    int gp = lane >> 2, tg = lane & 3;
    #pragma unroll
    for (int mt = 0; mt < 2; mt++) {
        int row0 = i0 + w * 32 + mt * 16 + gp;
        #pragma unroll
        for (int nb = 0; nb < NBLK; nb++) {
            int col = nb * 8 + tg * 2;
            size_t o0 = (size_t)row0 * STRIDE_OUT + col;
            size_t o1 = (size_t)(row0 + 8) * STRIDE_OUT + col;
            g_numP[sp][o0]     = accP[mt][nb][0];
            g_numP[sp][o0 + 1] = accP[mt][nb][1];
            g_numP[sp][o1]     = accP[mt][nb][2];
            g_numP[sp][o1 + 1] = accP[mt][nb][3];
            g_numN[sp][o0]     = accN[mt][nb][0];
            g_numN[sp][o0 + 1] = accN[mt][nb][1];
            g_numN[sp][o1]     = accN[mt][nb][2];
            g_numN[sp][o1 + 1] = accN[mt][nb][3];
        }
    }
}

// ---------------- kernel 5: combine splits, scale, divide, ELU ----------------
__global__ void k_final(float* __restrict__ out) {
    int idx = blockIdx.x * 256 + threadIdx.x;   // over NN*FO
    int i = idx >> 6, c = idx & 63;
    size_t b = (size_t)i * STRIDE_OUT;
    float p = g_p[i], q = g_q[i];
    float nP = g_numP[0][b + c]  + g_numP[1][b + c];
    float nN = g_numN[0][b + c]  + g_numN[1][b + c];
    float dP = g_numP[0][b + 64] + g_numP[1][b + 64];
    float dN = g_numN[0][b + 64] + g_numN[1][b + 64];
    float hv = (p * nP + q * nN) / (p * dP + q * dN);
    out[idx] = hv > 0.f ? hv : expm1f(hv);
}

extern "C" void kernel_launch(void* const* d_in, const int* in_sizes, int n_in,
                              void* d_out, int out_size) {
    const float* x   = (const float*)d_in[0];
    const int*   adj = (const int*)  d_in[1];
    const float* W   = (const float*)d_in[2];
    const float* a   = (const float*)d_in[3];
    float* out = (float*)d_out;

    static int smem_set = 0;
    if (!smem_set) {
        cudaFuncSetAttribute(k_main_tc, cudaFuncAttributeMaxDynamicSharedMemorySize, SM_TOTAL);
        smem_set = 1;
    }

    k_gemm_h<<<NN/64, 256>>>(x, W);
    k_scalars<<<NN/8, 256>>>(a);
    dim3 gt(NN/256, NB);
    k_tables<<<gt, 256>>>();
    dim3 gm(NN/MT, KSPLIT);
    k_main_tc<<<gm, 128, SM_TOTAL>>>(adj);
    k_final<<<(NN*FO)/256, 256>>>(out);
}

// round 5
// speedup vs baseline: 4.5010x; 3.5647x over previous
#include <cuda_runtime.h>
#include <cuda_bf16.h>
#include <cstdint>

#define NN 8192
#define FI 128
#define FO 64
#define LRALPHA 0.2f
#define KSPLIT 2
#define MT 128          // M rows per CTA
#define KT 64           // j per K-tile
#define NB 72           // padded N (64 feat + 1 den + 7 pad)
#define NBLK (NB/8)     // 9 n8 blocks
#define STRIDE_OUT 72

// ---------------- device scratch ----------------
__device__ float g_h[NN*FO];
__device__ __align__(16) float g_t[NN];
__device__ float g_s[NN], g_p[NN], g_q[NN];
__device__ __align__(16) __nv_bfloat16 g_Bph[(size_t)NB*NN], g_Bpl[(size_t)NB*NN];
__device__ __align__(16) __nv_bfloat16 g_Bnh[(size_t)NB*NN], g_Bnl[(size_t)NB*NN];
__device__ float g_numP[KSPLIT][(size_t)NN*STRIDE_OUT];
__device__ float g_numN[KSPLIT][(size_t)NN*STRIDE_OUT];

// ---------------- helpers ----------------
__device__ __forceinline__ uint32_t smem_u32(const void* p) {
    uint32_t a;
    asm("{ .reg .u64 t; cvta.to.shared.u64 t, %1; cvt.u32.u64 %0, t; }" : "=r"(a) : "l"(p));
    return a;
}
#define SWZ(x) ((uint32_t)(x) ^ ((((uint32_t)(x)) >> 3) & 0x70u))

__device__ __forceinline__ void ldm_x4(uint32_t addr, uint32_t r[4]) {
    asm volatile("ldmatrix.sync.aligned.m8n8.x4.shared.b16 {%0,%1,%2,%3}, [%4];"
        : "=r"(r[0]), "=r"(r[1]), "=r"(r[2]), "=r"(r[3]) : "r"(addr));
}
__device__ __forceinline__ void ldm_x2(uint32_t addr, uint32_t r[2]) {
    asm volatile("ldmatrix.sync.aligned.m8n8.x2.shared.b16 {%0,%1}, [%2];"
        : "=r"(r[0]), "=r"(r[1]) : "r"(addr));
}
__device__ __forceinline__ void mma16816(float* c, const uint32_t* a, const uint32_t* b) {
    asm("mma.sync.aligned.m16n8k16.row.col.f32.bf16.bf16.f32 "
        "{%0,%1,%2,%3}, {%4,%5,%6,%7}, {%8,%9}, {%0,%1,%2,%3};"
        : "+f"(c[0]), "+f"(c[1]), "+f"(c[2]), "+f"(c[3])
        : "r"(a[0]), "r"(a[1]), "r"(a[2]), "r"(a[3]), "r"(b[0]), "r"(b[1]));
}
__device__ __forceinline__ void cp16(uint32_t dst, const void* src) {
    asm volatile("cp.async.cg.shared.global [%0], [%1], 16;" :: "r"(dst), "l"(src) : "memory");
}
#define CP_COMMIT() asm volatile("cp.async.commit_group;" ::: "memory")
#define CP_WAIT0()  asm volatile("cp.async.wait_group 0;" ::: "memory")

// ---------------- kernel 1: h = x @ W ----------------
__global__ void k_gemm_h(const float* __restrict__ x, const float* __restrict__ W) {
    __shared__ float sW[FI*FO];
    __shared__ float sx[64][FI];
    int tid = threadIdx.x;
    for (int i = tid; i < FI*FO; i += 256) sW[i] = W[i];
    int r0 = blockIdx.x * 64;
    for (int i = tid; i < 64*FI; i += 256)
        sx[i >> 7][i & 127] = x[(size_t)(r0 + (i >> 7))*FI + (i & 127)];
    __syncthreads();
    int col = tid & 63;
    for (int rr = tid >> 6; rr < 64; rr += 4) {
        float acc = 0.f;
        #pragma unroll
        for (int k = 0; k < FI; k++) acc += sx[rr][k] * sW[k*FO + col];
        g_h[(size_t)(r0 + rr)*FO + col] = acc;
    }
}

// -------- kernel 2: per-row scalars s,t,p,q --------
__global__ void k_scalars(const float* __restrict__ a) {
    int gwarp = (blockIdx.x * blockDim.x + threadIdx.x) >> 5;
    int lane  = threadIdx.x & 31;
    if (gwarp >= NN) return;
    float h0 = g_h[(size_t)gwarp*FO + lane];
    float h1 = g_h[(size_t)gwarp*FO + 32 + lane];
    float s = h0 * a[lane]      + h1 * a[lane + 32];
    float t = h0 * a[lane + 64] + h1 * a[lane + 96];
    #pragma unroll
    for (int o = 16; o; o >>= 1) {
        s += __shfl_xor_sync(0xffffffffu, s, o);
        t += __shfl_xor_sync(0xffffffffu, t, o);
    }
    if (lane == 0) {
        g_s[gwarp] = s; g_t[gwarp] = t;
        g_p[gwarp] = __expf(s); g_q[gwarp] = __expf(LRALPHA * s);
    }
}

// -------- kernel 3: bf16 hi/lo value tables, N-major [n][j] --------
__global__ void k_tables() {
    int n = blockIdx.y;
    int j = blockIdx.x * 256 + threadIdx.x;
    float t = g_t[j];
    float u = __expf(t), v = __expf(LRALPHA * t);
    float vp, vn;
    if (n < FO)      { float h = g_h[(size_t)j*FO + n]; vp = u * h; vn = v * h; }
    else if (n == FO){ vp = u; vn = v; }
    else             { vp = 0.f; vn = 0.f; }
    __nv_bfloat16 ph = __float2bfloat16(vp);
    __nv_bfloat16 pl = __float2bfloat16(vp - __bfloat162float(ph));
    __nv_bfloat16 nh = __float2bfloat16(vn);
    __nv_bfloat16 nl = __float2bfloat16(vn - __bfloat162float(nh));
    size_t o = (size_t)n*NN + j;
    g_Bph[o] = ph; g_Bpl[o] = pl; g_Bnh[o] = nh; g_Bnl[o] = nl;
}

// ---------------- kernel 4: pipelined HMMA masked GEMM ----------------
// SMEM layout (dynamic):
#define SM_SS    0                           // 128 floats
#define SM_ADJ   1024                        // adj raw, 2 stages x 32KB
#define ADJ_B    (MT*KT*4)                   // 32768
#define SM_AP    (SM_ADJ + 2*ADJ_B)          // 66560
#define A_BYTES  (MT*128)                    // 16384
#define SM_AN    (SM_AP + A_BYTES)
#define SM_B     (SM_AN + A_BYTES)           // B, 2 stages x 4 streams
#define B_BYTES  (NB*128)                    // 9216
#define BSTG     (4*B_BYTES)                 // 36864
#define SM_TOTAL (SM_B + 2*BSTG)             // 173056

__global__ void __launch_bounds__(256) k_main_tc(const int* __restrict__ adj) {
    extern __shared__ char smem[];
    uint32_t sb = smem_u32(smem);
    int tid = threadIdx.x, w = tid >> 5, lane = tid & 31;
    int i0 = blockIdx.x * MT;
    int sp = blockIdx.y;
    int jbase = sp * (NN / KSPLIT);
    const int nTiles = (NN / KSPLIT) / KT;   // 64

    float* s_s = (float*)(smem + SM_SS);
    if (tid < MT) s_s[tid] = g_s[i0 + tid];

    float accP[NBLK][4], accN[NBLK][4];
    #pragma unroll
    for (int nb = 0; nb < NBLK; nb++)
        #pragma unroll
        for (int e = 0; e < 4; e++) { accP[nb][e] = 0.f; accN[nb][e] = 0.f; }

    // lane-invariant ldmatrix address pieces
    uint32_t aRowByte = (uint32_t)(w * 16 + (lane & 15)) * 128;
    uint32_t aKHalf   = ((lane >> 4) & 1) * 16;
    // B x4: lanes 0-7 nb k0 | 8-15 nb k1 | 16-23 nb+1 k0 | 24-31 nb+1 k1
    uint32_t bByte    = (uint32_t)(lane & 7) * 128 + ((lane >> 3) & 1) * 16
                      + ((lane >> 4) & 1) * 1024;
    uint32_t bByteX2  = (uint32_t)(lane & 7) * 128 + ((lane >> 3) & 1) * 16;

    const __nv_bfloat16* bsrc[4] = {g_Bph, g_Bpl, g_Bnh, g_Bnl};

    // ---- prefetch helper (stage st gets tile tt) ----
    auto prefetch = [&](int tt, int st) {
        int j0 = jbase + tt * KT;
        uint32_t adst = sb + SM_ADJ + st * ADJ_B;
        #pragma unroll
        for (int it = 0; it < 8; it++) {
            int idx = it * 256 + tid;                 // 0..2047 int4s
            cp16(adst + idx * 16, adj + (size_t)(i0 + (idx >> 4)) * NN + j0 + (idx & 15) * 4);
        }
        uint32_t bdst = sb + SM_B + st * BSTG;
        #pragma unroll
        for (int stg = 0; stg < 4; stg++) {
            const __nv_bfloat16* s = bsrc[stg];
            for (int v = tid; v < NB * 8; v += 256) {
                int n = v >> 3, ch = v & 7;
                cp16(bdst + stg * B_BYTES + SWZ((uint32_t)(n * 128 + ch * 16)),
                     s + (size_t)n * NN + j0 + ch * 8);
            }
        }
        CP_COMMIT();
    };

    prefetch(0, 0);

    for (int t = 0; t < nTiles; t++) {
        int st = t & 1;
        CP_WAIT0();
        __syncthreads();          // stage st data ready; prev MMA done (A, buf 1-st free)

        if (t + 1 < nTiles) prefetch(t + 1, 1 - st);

        // ---- build bf16 mask tiles from smem adj raw ----
        const char* araw = smem + SM_ADJ + st * ADJ_B;
        int j0 = jbase + t * KT;
        #pragma unroll
        for (int it = 0; it < 8; it++) {
            int idx = it * 256 + tid;
            int r = idx >> 4, seg = idx & 15;
            int4 av = *(const int4*)(araw + idx * 16);
            float4 t4 = *(const float4*)(g_t + j0 + seg * 4);
            float sr = s_s[r];
            bool m0 = av.x > 0, m1 = av.y > 0, m2 = av.z > 0, m3 = av.w > 0;
            bool c0 = sr + t4.x > 0.f, c1 = sr + t4.y > 0.f;
            bool c2 = sr + t4.z > 0.f, c3 = sr + t4.w > 0.f;
            uint32_t p01 = ((m0 && c0) ? 0x3F80u : 0u) | ((m1 && c1) ? 0x3F800000u : 0u);
            uint32_t p23 = ((m2 && c2) ? 0x3F80u : 0u) | ((m3 && c3) ? 0x3F800000u : 0u);
            uint32_t n01 = ((m0 && !c0) ? 0x3F80u : 0u) | ((m1 && !c1) ? 0x3F800000u : 0u);
            uint32_t n23 = ((m2 && !c2) ? 0x3F80u : 0u) | ((m3 && !c3) ? 0x3F800000u : 0u);
            uint32_t boff = SWZ((uint32_t)(r * 128 + seg * 8));
            *(uint2*)(smem + SM_AP + boff) = make_uint2(p01, p23);
            *(uint2*)(smem + SM_AN + boff) = make_uint2(n01, n23);
        }
        __syncthreads();

        // ---- MMA phase: 4 ksteps of k16 ----
        uint32_t bbase = sb + SM_B + st * BSTG;
        #pragma unroll
        for (int ks = 0; ks < 4; ks++) {
            uint32_t kB = (uint32_t)ks * 32;
            uint32_t aP[4], aN[4];
            uint32_t aoff = SWZ(aRowByte + kB + aKHalf);
            ldm_x4(sb + SM_AP + aoff, aP);
            ldm_x4(sb + SM_AN + aoff, aN);
            #pragma unroll
            for (int pr = 0; pr < 4; pr++) {          // nb pairs {0,1},{2,3},{4,5},{6,7}
                uint32_t boff = SWZ(bByte + pr * 2048u + kB);
                uint32_t bph[4], bpl[4], bnh[4], bnl[4];
                ldm_x4(bbase + 0 * B_BYTES + boff, bph);
                ldm_x4(bbase + 1 * B_BYTES + boff, bpl);
                ldm_x4(bbase + 2 * B_BYTES + boff, bnh);
                ldm_x4(bbase + 3 * B_BYTES + boff, bnl);
                mma16816(accP[2*pr],   aP, bph);
                mma16816(accP[2*pr+1], aP, bph + 2);
                mma16816(accP[2*pr],   aP, bpl);
                mma16816(accP[2*pr+1], aP, bpl + 2);
                mma16816(accN[2*pr],   aN, bnh);
                mma16816(accN[2*pr+1], aN, bnh + 2);
                mma16816(accN[2*pr],   aN, bnl);
                mma16816(accN[2*pr+1], aN, bnl + 2);
            }
            {   // nb = 8 via x2
                uint32_t boff = SWZ(bByteX2 + 8192u + kB);
                uint32_t b0[2], b1[2], b2[2], b3[2];
                ldm_x2(bbase + 0 * B_BYTES + boff, b0);
                ldm_x2(bbase + 1 * B_BYTES + boff, b1);
                ldm_x2(bbase + 2 * B_BYTES + boff, b2);
                ldm_x2(bbase + 3 * B_BYTES + boff, b3);
                mma16816(accP[8], aP, b0);
                mma16816(accP[8], aP, b1);
                mma16816(accN[8], aN, b2);
                mma16816(accN[8], aN, b3);
            }
        }
    }

    // ---- epilogue: write fp32 partials ----
    int gp = lane >> 2, tg = lane & 3;
    int row0 = i0 + w * 16 + gp;
    #pragma unroll
    for (int nb = 0; nb < NBLK; nb++) {
        int col = nb * 8 + tg * 2;
        size_t o0 = (size_t)row0 * STRIDE_OUT + col;
        size_t o1 = (size_t)(row0 + 8) * STRIDE_OUT + col;
        g_numP[sp][o0]     = accP[nb][0];
        g_numP[sp][o0 + 1] = accP[nb][1];
        g_numP[sp][o1]     = accP[nb][2];
        g_numP[sp][o1 + 1] = accP[nb][3];
        g_numN[sp][o0]     = accN[nb][0];
        g_numN[sp][o0 + 1] = accN[nb][1];
        g_numN[sp][o1]     = accN[nb][2];
        g_numN[sp][o1 + 1] = accN[nb][3];
    }
}

// ---------------- kernel 5: combine splits, scale, divide, ELU ----------------
__global__ void k_final(float* __restrict__ out) {
    int idx = blockIdx.x * 256 + threadIdx.x;
    int i = idx >> 6, c = idx & 63;
    size_t b = (size_t)i * STRIDE_OUT;
    float p = g_p[i], q = g_q[i];
    float nP = g_numP[0][b + c]  + g_numP[1][b + c];
    float nN = g_numN[0][b + c]  + g_numN[1][b + c];
    float dP = g_numP[0][b + 64] + g_numP[1][b + 64];
    float dN = g_numN[0][b + 64] + g_numN[1][b + 64];
    float hv = (p * nP + q * nN) / (p * dP + q * dN);
    out[idx] = hv > 0.f ? hv : expm1f(hv);
}

extern "C" void kernel_launch(void* const* d_in, const int* in_sizes, int n_in,
                              void* d_out, int out_size) {
    const float* x   = (const float*)d_in[0];
    const int*   adj = (const int*)  d_in[1];
    const float* W   = (const float*)d_in[2];
    const float* a   = (const float*)d_in[3];
    float* out = (float*)d_out;

    cudaFuncSetAttribute(k_main_tc, cudaFuncAttributeMaxDynamicSharedMemorySize, SM_TOTAL);

    k_gemm_h<<<NN/64, 256>>>(x, W);
    k_scalars<<<NN/8, 256>>>(a);
    dim3 gt(NN/256, NB);
    k_tables<<<gt, 256>>>();
    dim3 gm(NN/MT, KSPLIT);
    k_main_tc<<<gm, 256, SM_TOTAL>>>(adj);
    k_final<<<(NN*FO)/256, 256>>>(out);
}

// round 6
// speedup vs baseline: 5.3065x; 1.1790x over previous
#include <cuda_runtime.h>
#include <cuda_bf16.h>
#include <cstdint>

#define NN 8192
#define FI 128
#define FO 64
#define LRALPHA 0.2f
#define KSPLIT 4
#define MT 128          // M rows per CTA
#define KT 64           // j per K-tile
#define NB 72           // padded N (64 feat + 1 den + 7 pad)
#define STRIDE_OUT 72

// ---------------- device scratch ----------------
__device__ float g_h[NN*FO];
__device__ __align__(16) float g_t[NN];
__device__ float g_s[NN], g_p[NN], g_q[NN];
__device__ __align__(16) __nv_bfloat16 g_Bph[(size_t)NB*NN], g_Bpl[(size_t)NB*NN];
__device__ __align__(16) __nv_bfloat16 g_Bnh[(size_t)NB*NN], g_Bnl[(size_t)NB*NN];
__device__ float g_numP[KSPLIT][(size_t)NN*STRIDE_OUT];
__device__ float g_numN[KSPLIT][(size_t)NN*STRIDE_OUT];

// ---------------- helpers ----------------
__device__ __forceinline__ uint32_t smem_u32(const void* p) {
    uint32_t a;
    asm("{ .reg .u64 t; cvta.to.shared.u64 t, %1; cvt.u32.u64 %0, t; }" : "=r"(a) : "l"(p));
    return a;
}
#define SWZ(x) ((uint32_t)(x) ^ ((((uint32_t)(x)) >> 3) & 0x70u))

__device__ __forceinline__ void ldm_x4(uint32_t addr, uint32_t r[4]) {
    asm volatile("ldmatrix.sync.aligned.m8n8.x4.shared.b16 {%0,%1,%2,%3}, [%4];"
        : "=r"(r[0]), "=r"(r[1]), "=r"(r[2]), "=r"(r[3]) : "r"(addr));
}
__device__ __forceinline__ void ldm_x2(uint32_t addr, uint32_t r[2]) {
    asm volatile("ldmatrix.sync.aligned.m8n8.x2.shared.b16 {%0,%1}, [%2];"
        : "=r"(r[0]), "=r"(r[1]) : "r"(addr));
}
__device__ __forceinline__ void mma16816(float* c, const uint32_t* a, const uint32_t* b) {
    asm("mma.sync.aligned.m16n8k16.row.col.f32.bf16.bf16.f32 "
        "{%0,%1,%2,%3}, {%4,%5,%6,%7}, {%8,%9}, {%0,%1,%2,%3};"
        : "+f"(c[0]), "+f"(c[1]), "+f"(c[2]), "+f"(c[3])
        : "r"(a[0]), "r"(a[1]), "r"(a[2]), "r"(a[3]), "r"(b[0]), "r"(b[1]));
}
__device__ __forceinline__ void cp16(uint32_t dst, const void* src) {
    asm volatile("cp.async.cg.shared.global [%0], [%1], 16;" :: "r"(dst), "l"(src) : "memory");
}
#define CP_COMMIT() asm volatile("cp.async.commit_group;" ::: "memory")
#define CP_WAIT(n)  asm volatile("cp.async.wait_group %0;" :: "n"(n) : "memory")

// ---------------- kernel 1: h = x @ W ----------------
__global__ void k_gemm_h(const float* __restrict__ x, const float* __restrict__ W) {
    __shared__ float sW[FI*FO];
    __shared__ float sx[64][FI];
    int tid = threadIdx.x;
    for (int i = tid; i < FI*FO; i += 256) sW[i] = W[i];
    int r0 = blockIdx.x * 64;
    for (int i = tid; i < 64*FI; i += 256)
        sx[i >> 7][i & 127] = x[(size_t)(r0 + (i >> 7))*FI + (i & 127)];
    __syncthreads();
    int col = tid & 63;
    for (int rr = tid >> 6; rr < 64; rr += 4) {
        float acc = 0.f;
        #pragma unroll
        for (int k = 0; k < FI; k++) acc += sx[rr][k] * sW[k*FO + col];
        g_h[(size_t)(r0 + rr)*FO + col] = acc;
    }
}

// -------- kernel 2: per-row scalars s,t,p,q --------
__global__ void k_scalars(const float* __restrict__ a) {
    int gwarp = (blockIdx.x * blockDim.x + threadIdx.x) >> 5;
    int lane  = threadIdx.x & 31;
    if (gwarp >= NN) return;
    float h0 = g_h[(size_t)gwarp*FO + lane];
    float h1 = g_h[(size_t)gwarp*FO + 32 + lane];
    float s = h0 * a[lane]      + h1 * a[lane + 32];
    float t = h0 * a[lane + 64] + h1 * a[lane + 96];
    #pragma unroll
    for (int o = 16; o; o >>= 1) {
        s += __shfl_xor_sync(0xffffffffu, s, o);
        t += __shfl_xor_sync(0xffffffffu, t, o);
    }
    if (lane == 0) {
        g_s[gwarp] = s; g_t[gwarp] = t;
        g_p[gwarp] = __expf(s); g_q[gwarp] = __expf(LRALPHA * s);
    }
}

// -------- kernel 3: bf16 hi/lo value tables, N-major [n][j] --------
__global__ void k_tables() {
    int n = blockIdx.y;
    int j = blockIdx.x * 256 + threadIdx.x;
    float t = g_t[j];
    float u = __expf(t), v = __expf(LRALPHA * t);
    float vp, vn;
    if (n < FO)      { float h = g_h[(size_t)j*FO + n]; vp = u * h; vn = v * h; }
    else if (n == FO){ vp = u; vn = v; }
    else             { vp = 0.f; vn = 0.f; }
    __nv_bfloat16 ph = __float2bfloat16(vp);
    __nv_bfloat16 pl = __float2bfloat16(vp - __bfloat162float(ph));
    __nv_bfloat16 nh = __float2bfloat16(vn);
    __nv_bfloat16 nl = __float2bfloat16(vn - __bfloat162float(nh));
    size_t o = (size_t)n*NN + j;
    g_Bph[o] = ph; g_Bpl[o] = pl; g_Bnh[o] = nh; g_Bnl[o] = nl;
}

// ---------------- kernel 4: pipelined HMMA masked GEMM ----------------
// SMEM: SS(512B pad to 1K) | AP 16K | AN 16K | B 2 stages x 4 streams x 9216
#define SM_SS    0
#define SM_AP    1024
#define A_BYTES  (MT*128)                    // 16384
#define SM_AN    (SM_AP + A_BYTES)
#define SM_B     (SM_AN + A_BYTES)
#define B_BYTES  (NB*128)                    // 9216
#define BSTG     (4*B_BYTES)                 // 36864
#define SM_TOTAL (SM_B + 2*BSTG)             // 107520

__global__ void __launch_bounds__(256, 2) k_main_tc(const int* __restrict__ adj) {
    extern __shared__ char smem[];
    uint32_t sb = smem_u32(smem);
    int tid = threadIdx.x, w = tid >> 5, lane = tid & 31;
    int wm = w & 3, wn = w >> 2;                 // 4 M-groups x 2 N-groups
    int i0 = blockIdx.x * MT;
    int sp = blockIdx.y;
    int jbase = sp * (NN / KSPLIT);
    const int nTiles = (NN / KSPLIT) / KT;       // 32

    float* s_s = (float*)(smem + SM_SS);
    if (tid < MT) s_s[tid] = g_s[i0 + tid];

    // acc[mt][nb][4]; wn0 uses nb 0..3 (blocks 0-3), wn1 uses nb 0..4 (blocks 4-8)
    float accP[2][5][4], accN[2][5][4];
    #pragma unroll
    for (int mt = 0; mt < 2; mt++)
        #pragma unroll
        for (int nb = 0; nb < 5; nb++)
            #pragma unroll
            for (int e = 0; e < 4; e++) { accP[mt][nb][e] = 0.f; accN[mt][nb][e] = 0.f; }

    int nbBase = wn * 4;
    // ldmatrix lane addresses
    uint32_t aRowByte = (uint32_t)(wm * 32 + (lane & 15)) * 128;     // + mt*2048
    uint32_t aKHalf   = ((lane >> 4) & 1) * 16;
    uint32_t bByte    = (uint32_t)(lane & 7) * 128 + ((lane >> 3) & 1) * 16
                      + ((lane >> 4) & 1) * 1024;
    uint32_t bByteX2  = (uint32_t)(lane & 7) * 128 + ((lane >> 3) & 1) * 16;

    const __nv_bfloat16* bsrc[4] = {g_Bph, g_Bpl, g_Bnh, g_Bnl};

    auto prefetchB = [&](int tt, int st) {
        int j0 = jbase + tt * KT;
        uint32_t bdst = sb + SM_B + st * BSTG;
        #pragma unroll
        for (int stg = 0; stg < 4; stg++) {
            const __nv_bfloat16* s = bsrc[stg];
            for (int v = tid; v < NB * 8; v += 256) {
                int n = v >> 3, ch = v & 7;
                cp16(bdst + stg * B_BYTES + SWZ((uint32_t)(n * 128 + ch * 16)),
                     s + (size_t)n * NN + j0 + ch * 8);
            }
        }
    };

    prefetchB(0, 0);
    CP_COMMIT();

    for (int t = 0; t < nTiles; t++) {
        int st = t & 1;
        int j0 = jbase + t * KT;
        __syncthreads();     // prior MMA done reading A and B stage (1-st)

        // ---- build bf16 mask tiles A_P/A_N from direct adj LDG ----
        #pragma unroll
        for (int g = 0; g < 2; g++) {
            int4 av[4];
            #pragma unroll
            for (int u = 0; u < 4; u++) {
                int idx = (g * 4 + u) * 256 + tid;
                av[u] = __ldg((const int4*)(adj + (size_t)(i0 + (idx >> 4)) * NN
                                            + j0 + (idx & 15) * 4));
            }
            #pragma unroll
            for (int u = 0; u < 4; u++) {
                int idx = (g * 4 + u) * 256 + tid;
                int r = idx >> 4, seg = idx & 15;
                float4 t4 = *(const float4*)(g_t + j0 + seg * 4);
                float sr = s_s[r];
                bool m0 = av[u].x > 0, m1 = av[u].y > 0, m2 = av[u].z > 0, m3 = av[u].w > 0;
                bool c0 = sr + t4.x > 0.f, c1 = sr + t4.y > 0.f;
                bool c2 = sr + t4.z > 0.f, c3 = sr + t4.w > 0.f;
                uint32_t p01 = ((m0 && c0) ? 0x3F80u : 0u) | ((m1 && c1) ? 0x3F800000u : 0u);
                uint32_t p23 = ((m2 && c2) ? 0x3F80u : 0u) | ((m3 && c3) ? 0x3F800000u : 0u);
                uint32_t n01 = ((m0 && !c0) ? 0x3F80u : 0u) | ((m1 && !c1) ? 0x3F800000u : 0u);
                uint32_t n23 = ((m2 && !c2) ? 0x3F80u : 0u) | ((m3 && !c3) ? 0x3F800000u : 0u);
                uint32_t boff = SWZ((uint32_t)(r * 128 + seg * 8));
                *(uint2*)(smem + SM_AP + boff) = make_uint2(p01, p23);
                *(uint2*)(smem + SM_AN + boff) = make_uint2(n01, n23);
            }
        }

        if (t + 1 < nTiles) {
            prefetchB(t + 1, 1 - st);
            CP_COMMIT();
            CP_WAIT(1);       // stage st complete, next stage in flight
        } else {
            CP_WAIT(0);
        }
        __syncthreads();      // A tiles + B stage st visible to all

        // ---- MMA phase: 4 ksteps ----
        uint32_t bbase = sb + SM_B + st * BSTG;
        #pragma unroll
        for (int ks = 0; ks < 4; ks++) {
            uint32_t kB = (uint32_t)ks * 32;
            uint32_t aP[2][4], aN[2][4];
            #pragma unroll
            for (int mt = 0; mt < 2; mt++) {
                uint32_t aoff = SWZ(aRowByte + mt * 2048u + kB + aKHalf);
                ldm_x4(sb + SM_AP + aoff, aP[mt]);
                ldm_x4(sb + SM_AN + aoff, aN[mt]);
            }
            #pragma unroll
            for (int pr = 0; pr < 2; pr++) {       // block pairs within N-group
                uint32_t boff = SWZ(bByte + (nbBase + 2 * pr) * 1024u + kB);
                uint32_t bph[4], bpl[4], bnh[4], bnl[4];
                ldm_x4(bbase + 0 * B_BYTES + boff, bph);
                ldm_x4(bbase + 1 * B_BYTES + boff, bpl);
                ldm_x4(bbase + 2 * B_BYTES + boff, bnh);
                ldm_x4(bbase + 3 * B_BYTES + boff, bnl);
                // hi streams (P then N), then lo streams: RAW gap 7
                mma16816(accP[0][2*pr],   aP[0], bph);
                mma16816(accP[1][2*pr],   aP[1], bph);
                mma16816(accP[0][2*pr+1], aP[0], bph + 2);
                mma16816(accP[1][2*pr+1], aP[1], bph + 2);
                mma16816(accN[0][2*pr],   aN[0], bnh);
                mma16816(accN[1][2*pr],   aN[1], bnh);
                mma16816(accN[0][2*pr+1], aN[0], bnh + 2);
                mma16816(accN[1][2*pr+1], aN[1], bnh + 2);
                mma16816(accP[0][2*pr],   aP[0], bpl);
                mma16816(accP[1][2*pr],   aP[1], bpl);
                mma16816(accP[0][2*pr+1], aP[0], bpl + 2);
                mma16816(accP[1][2*pr+1], aP[1], bpl + 2);
                mma16816(accN[0][2*pr],   aN[0], bnl);
                mma16816(accN[1][2*pr],   aN[1], bnl);
                mma16816(accN[0][2*pr+1], aN[0], bnl + 2);
                mma16816(accN[1][2*pr+1], aN[1], bnl + 2);
            }
            if (wn == 1) {     // block 8 (denominator col) via x2
                uint32_t boff = SWZ(bByteX2 + 8192u + kB);
                uint32_t b0[2], b1[2], b2[2], b3[2];
                ldm_x2(bbase + 0 * B_BYTES + boff, b0);
                ldm_x2(bbase + 1 * B_BYTES + boff, b1);
                ldm_x2(bbase + 2 * B_BYTES + boff, b2);
                ldm_x2(bbase + 3 * B_BYTES + boff, b3);
                mma16816(accP[0][4], aP[0], b0);
                mma16816(accP[1][4], aP[1], b0);
                mma16816(accN[0][4], aN[0], b2);
                mma16816(accN[1][4], aN[1], b2);
                mma16816(accP[0][4], aP[0], b1);
                mma16816(accP[1][4], aP[1], b1);
                mma16816(accN[0][4], aN[0], b3);
                mma16816(accN[1][4], aN[1], b3);
            }
        }
    }

    // ---- epilogue: write fp32 partials ----
    int gp = lane >> 2, tg = lane & 3;
    int nBlk = 4 + wn;
    #pragma unroll
    for (int mt = 0; mt < 2; mt++) {
        int row0 = i0 + wm * 32 + mt * 16 + gp;
        for (int nb = 0; nb < nBlk; nb++) {
            int col = (nbBase + nb) * 8 + tg * 2;
            size_t o0 = (size_t)row0 * STRIDE_OUT + col;
            size_t o1 = (size_t)(row0 + 8) * STRIDE_OUT + col;
            g_numP[sp][o0]     = accP[mt][nb][0];
            g_numP[sp][o0 + 1] = accP[mt][nb][1];
            g_numP[sp][o1]     = accP[mt][nb][2];
            g_numP[sp][o1 + 1] = accP[mt][nb][3];
            g_numN[sp][o0]     = accN[mt][nb][0];
            g_numN[sp][o0 + 1] = accN[mt][nb][1];
            g_numN[sp][o1]     = accN[mt][nb][2];
            g_numN[sp][o1 + 1] = accN[mt][nb][3];
        }
    }
}

// ---------------- kernel 5: combine splits, scale, divide, ELU ----------------
__global__ void k_final(float* __restrict__ out) {
    int idx = blockIdx.x * 256 + threadIdx.x;
    int i = idx >> 6, c = idx & 63;
    size_t b = (size_t)i * STRIDE_OUT;
    float p = g_p[i], q = g_q[i];
    float nP = 0.f, nN = 0.f, dP = 0.f, dN = 0.f;
    #pragma unroll
    for (int s2 = 0; s2 < KSPLIT; s2++) {
        nP += g_numP[s2][b + c];  nN += g_numN[s2][b + c];
        dP += g_numP[s2][b + 64]; dN += g_numN[s2][b + 64];
    }
    float hv = (p * nP + q * nN) / (p * dP + q * dN);
    out[idx] = hv > 0.f ? hv : expm1f(hv);
}

extern "C" void kernel_launch(void* const* d_in, const int* in_sizes, int n_in,
                              void* d_out, int out_size) {
    const float* x   = (const float*)d_in[0];
    const int*   adj = (const int*)  d_in[1];
    const float* W   = (const float*)d_in[2];
    const float* a   = (const float*)d_in[3];
    float* out = (float*)d_out;

    cudaFuncSetAttribute(k_main_tc, cudaFuncAttributeMaxDynamicSharedMemorySize, SM_TOTAL);

    k_gemm_h<<<NN/64, 256>>>(x, W);
    k_scalars<<<NN/8, 256>>>(a);
    dim3 gt(NN/256, NB);
    k_tables<<<gt, 256>>>();
    dim3 gm(NN/MT, KSPLIT);
    k_main_tc<<<gm, 256, SM_TOTAL>>>(adj);
    k_final<<<(NN*FO)/256, 256>>>(out);
}

// round 7
// speedup vs baseline: 6.1691x; 1.1626x over previous
#include <cuda_runtime.h>
#include <cuda_bf16.h>
#include <cstdint>

#define NN 8192
#define FI 128
#define FO 64
#define LRALPHA 0.2f
#define KSPLIT 4
#define MT 128          // M rows per CTA
#define KT 64           // j per K-tile
#define NB 72           // padded N (64 feat + 1 den + 7 pad)
#define STRIDE_OUT 72

// ---------------- device scratch ----------------
__device__ float g_h[NN*FO];
__device__ __align__(16) float g_t[NN];
__device__ float g_s[NN], g_p[NN], g_q[NN];
__device__ __align__(16) __nv_bfloat16 g_ubf[NN], g_vbf[NN];   // bf16 exp(t), exp(a t)
__device__ __align__(16) __nv_bfloat16 g_Bh [(size_t)NB*NN];   // bf16(h | 1) shared
__device__ __align__(16) __nv_bfloat16 g_BlP[(size_t)NB*NN];   // (u/uhat)h - Bh
__device__ __align__(16) __nv_bfloat16 g_BlN[(size_t)NB*NN];   // (v/vhat)h - Bh
__device__ float g_numP[KSPLIT][(size_t)NN*STRIDE_OUT];
__device__ float g_numN[KSPLIT][(size_t)NN*STRIDE_OUT];

// ---------------- helpers ----------------
__device__ __forceinline__ uint32_t smem_u32(const void* p) {
    uint32_t a;
    asm("{ .reg .u64 t; cvta.to.shared.u64 t, %1; cvt.u32.u64 %0, t; }" : "=r"(a) : "l"(p));
    return a;
}
#define SWZ(x) ((uint32_t)(x) ^ ((((uint32_t)(x)) >> 3) & 0x70u))

__device__ __forceinline__ void ldm_x4(uint32_t addr, uint32_t r[4]) {
    asm volatile("ldmatrix.sync.aligned.m8n8.x4.shared.b16 {%0,%1,%2,%3}, [%4];"
        : "=r"(r[0]), "=r"(r[1]), "=r"(r[2]), "=r"(r[3]) : "r"(addr));
}
__device__ __forceinline__ void ldm_x2(uint32_t addr, uint32_t r[2]) {
    asm volatile("ldmatrix.sync.aligned.m8n8.x2.shared.b16 {%0,%1}, [%2];"
        : "=r"(r[0]), "=r"(r[1]) : "r"(addr));
}
__device__ __forceinline__ void mma16816(float* c, const uint32_t* a, const uint32_t* b) {
    asm("mma.sync.aligned.m16n8k16.row.col.f32.bf16.bf16.f32 "
        "{%0,%1,%2,%3}, {%4,%5,%6,%7}, {%8,%9}, {%0,%1,%2,%3};"
        : "+f"(c[0]), "+f"(c[1]), "+f"(c[2]), "+f"(c[3])
        : "r"(a[0]), "r"(a[1]), "r"(a[2]), "r"(a[3]), "r"(b[0]), "r"(b[1]));
}
__device__ __forceinline__ void cp16(uint32_t dst, const void* src) {
    asm volatile("cp.async.cg.shared.global [%0], [%1], 16;" :: "r"(dst), "l"(src) : "memory");
}
#define CP_COMMIT() asm volatile("cp.async.commit_group;" ::: "memory")
#define CP_WAIT(n)  asm volatile("cp.async.wait_group %0;" :: "n"(n) : "memory")
__device__ __forceinline__ void prefetchL1(const void* p) {
    asm volatile("prefetch.global.L1 [%0];" :: "l"(p));
}

// ---------------- kernel 1: h = x @ W  (+ fused per-row scalars) ----------------
__global__ void k_gemm_h(const float* __restrict__ x, const float* __restrict__ W,
                         const float* __restrict__ a) {
    __shared__ float sW[FI*FO];     // 32KB, reused as sh[64][64] afterwards
    __shared__ float sx[64][FI];    // 32KB
    int tid = threadIdx.x;
    for (int i = tid; i < FI*FO; i += 256) sW[i] = W[i];
    int r0 = blockIdx.x * 64;
    for (int i = tid; i < 64*FI; i += 256)
        sx[i >> 7][i & 127] = x[(size_t)(r0 + (i >> 7))*FI + (i & 127)];
    __syncthreads();
    int col = tid & 63;
    float accv[16];
    int cnt = 0;
    for (int rr = tid >> 6; rr < 64; rr += 4) {
        float acc = 0.f;
        #pragma unroll
        for (int k = 0; k < FI; k++) acc += sx[rr][k] * sW[k*FO + col];
        g_h[(size_t)(r0 + rr)*FO + col] = acc;
        accv[cnt++] = acc;
    }
    __syncthreads();    // all sW reads done; reuse as sh
    float* sh = sW;     // [64][64]
    cnt = 0;
    for (int rr = tid >> 6; rr < 64; rr += 4) sh[rr*64 + col] = accv[cnt++];
    __syncthreads();
    int w = tid >> 5, lane = tid & 31;
    for (int rr = w * 8; rr < w * 8 + 8; rr++) {
        float h0 = sh[rr*64 + lane];
        float h1 = sh[rr*64 + 32 + lane];
        float s = h0 * a[lane]      + h1 * a[lane + 32];
        float t = h0 * a[lane + 64] + h1 * a[lane + 96];
        #pragma unroll
        for (int o = 16; o; o >>= 1) {
            s += __shfl_xor_sync(0xffffffffu, s, o);
            t += __shfl_xor_sync(0xffffffffu, t, o);
        }
        if (lane == 0) {
            int gi = r0 + rr;
            g_s[gi] = s; g_t[gi] = t;
            g_p[gi] = expf(s); g_q[gi] = expf(LRALPHA * s);
        }
    }
}

// -------- kernel 2: bf16 tables: Bh shared + per-branch residuals; û/v̂ --------
__global__ void k_tables() {
    int n = blockIdx.y;
    int j = blockIdx.x * 256 + threadIdx.x;
    float t = g_t[j];
    float u = expf(t), v = expf(LRALPHA * t);
    __nv_bfloat16 ub = __float2bfloat16(u);
    __nv_bfloat16 vb = __float2bfloat16(v);
    if (n == 0) { g_ubf[j] = ub; g_vbf[j] = vb; }
    float ur = u / __bfloat162float(ub);
    float vr = v / __bfloat162float(vb);
    float base;
    if (n < FO)       base = g_h[(size_t)j*FO + n];
    else if (n == FO) base = 1.f;
    else              base = 0.f;
    __nv_bfloat16 bh = __float2bfloat16(base);
    float bh32 = __bfloat162float(bh);
    size_t o = (size_t)n*NN + j;
    g_Bh [o] = bh;
    g_BlP[o] = __float2bfloat16(ur * base - bh32);
    g_BlN[o] = __float2bfloat16(vr * base - bh32);
}

// ---------------- kernel 3: pipelined HMMA masked GEMM ----------------
// SMEM: SS 1K | AP 16K | AN 16K | B 2 stages x 3 streams x 9216
#define SM_SS    0
#define SM_AP    1024
#define A_BYTES  (MT*128)                    // 16384
#define SM_AN    (SM_AP + A_BYTES)
#define SM_B     (SM_AN + A_BYTES)
#define B_BYTES  (NB*128)                    // 9216
#define BSTG     (3*B_BYTES)                 // 27648
#define SM_TOTAL (SM_B + 2*BSTG)             // 88320

__global__ void __launch_bounds__(256, 2) k_main_tc(const int* __restrict__ adj) {
    extern __shared__ char smem[];
    uint32_t sb = smem_u32(smem);
    int tid = threadIdx.x, w = tid >> 5, lane = tid & 31;
    int wm = w & 3, wn = w >> 2;                 // 4 M-groups x 2 N-groups
    int i0 = blockIdx.x * MT;
    int sp = blockIdx.y;
    int jbase = sp * (NN / KSPLIT);
    const int nTiles = (NN / KSPLIT) / KT;       // 32

    float* s_s = (float*)(smem + SM_SS);
    if (tid < MT) s_s[tid] = g_s[i0 + tid];

    float accP[2][5][4], accN[2][5][4];
    #pragma unroll
    for (int mt = 0; mt < 2; mt++)
        #pragma unroll
        for (int nb = 0; nb < 5; nb++)
            #pragma unroll
            for (int e = 0; e < 4; e++) { accP[mt][nb][e] = 0.f; accN[mt][nb][e] = 0.f; }

    int nbBase = wn * 4;
    uint32_t aRowByte = (uint32_t)(wm * 32 + (lane & 15)) * 128;
    uint32_t aKHalf   = ((lane >> 4) & 1) * 16;
    uint32_t bByte    = (uint32_t)(lane & 7) * 128 + ((lane >> 3) & 1) * 16
                      + ((lane >> 4) & 1) * 1024;
    uint32_t bByteX2  = (uint32_t)(lane & 7) * 128 + ((lane >> 3) & 1) * 16;

    auto prefetchB = [&](int tt, int st) {
        int j0 = jbase + tt * KT;
        uint32_t bdst = sb + SM_B + st * BSTG;
        for (int v = tid; v < NB * 8; v += 256) {
            int n = v >> 3, ch = v & 7;
            uint32_t so = SWZ((uint32_t)(n * 128 + ch * 16));
            size_t src = (size_t)n * NN + j0 + ch * 8;
            cp16(bdst + 0 * B_BYTES + so, g_Bh  + src);
            cp16(bdst + 1 * B_BYTES + so, g_BlP + src);
            cp16(bdst + 2 * B_BYTES + so, g_BlN + src);
        }
    };

    prefetchB(0, 0);
    CP_COMMIT();

    for (int t = 0; t < nTiles; t++) {
        int st = t & 1;
        int j0 = jbase + t * KT;
        __syncthreads();     // prior MMA done reading A and B stage (1-st)

        // ---- build A_P = mask_P * uhat, A_N = mask_N * vhat (128x64 bf16, SW128) ----
        #pragma unroll
        for (int it = 0; it < 4; it++) {
            int idx = it * 256 + tid;            // 0..1023; 8 edges each
            int r = idx >> 3, seg = idx & 7;
            const int* ap = adj + (size_t)(i0 + r) * NN + j0 + seg * 8;
            int4 a0 = __ldg((const int4*)ap);
            int4 a1 = __ldg((const int4*)(ap + 4));
            const float* tp = g_t + j0 + seg * 8;
            float4 t0 = *(const float4*)tp;
            float4 t1 = *(const float4*)(tp + 4);
            uint4 uu = *(const uint4*)(g_ubf + j0 + seg * 8);
            uint4 vv = *(const uint4*)(g_vbf + j0 + seg * 8);
            float sr = s_s[r];
            uint4 P, Nv;
            {
                bool m0 = a0.x > 0, m1 = a0.y > 0, m2 = a0.z > 0, m3 = a0.w > 0;
                bool c0 = sr + t0.x > 0.f, c1 = sr + t0.y > 0.f;
                bool c2 = sr + t0.z > 0.f, c3 = sr + t0.w > 0.f;
                uint32_t mp01 = (m0 && c0 ? 0xFFFFu : 0u) | (m1 && c1 ? 0xFFFF0000u : 0u);
                uint32_t mp23 = (m2 && c2 ? 0xFFFFu : 0u) | (m3 && c3 ? 0xFFFF0000u : 0u);
                uint32_t mn01 = (m0 && !c0 ? 0xFFFFu : 0u) | (m1 && !c1 ? 0xFFFF0000u : 0u);
                uint32_t mn23 = (m2 && !c2 ? 0xFFFFu : 0u) | (m3 && !c3 ? 0xFFFF0000u : 0u);
                P.x = uu.x & mp01; P.y = uu.y & mp23;
                Nv.x = vv.x & mn01; Nv.y = vv.y & mn23;
            }
            {
                bool m0 = a1.x > 0, m1 = a1.y > 0, m2 = a1.z > 0, m3 = a1.w > 0;
                bool c0 = sr + t1.x > 0.f, c1 = sr + t1.y > 0.f;
                bool c2 = sr + t1.z > 0.f, c3 = sr + t1.w > 0.f;
                uint32_t mp01 = (m0 && c0 ? 0xFFFFu : 0u) | (m1 && c1 ? 0xFFFF0000u : 0u);
                uint32_t mp23 = (m2 && c2 ? 0xFFFFu : 0u) | (m3 && c3 ? 0xFFFF0000u : 0u);
                uint32_t mn01 = (m0 && !c0 ? 0xFFFFu : 0u) | (m1 && !c1 ? 0xFFFF0000u : 0u);
                uint32_t mn23 = (m2 && !c2 ? 0xFFFFu : 0u) | (m3 && !c3 ? 0xFFFF0000u : 0u);
                P.z = uu.z & mp01; P.w = uu.w & mp23;
                Nv.z = vv.z & mn01; Nv.w = vv.w & mn23;
            }
            uint32_t boff = SWZ((uint32_t)(r * 128 + seg * 16));
            *(uint4*)(smem + SM_AP + boff) = P;
            *(uint4*)(smem + SM_AN + boff) = Nv;
        }

        if (t + 1 < nTiles) {
            prefetchB(t + 1, 1 - st);
            CP_COMMIT();
            CP_WAIT(1);
        } else {
            CP_WAIT(0);
        }
        __syncthreads();

        // prefetch next tile's adj into L1 (one 128B line per thread)
        if (t + 1 < nTiles) {
            int jn = j0 + KT;
            prefetchL1(adj + (size_t)(i0 + (tid >> 1)) * NN + jn + (tid & 1) * 32);
        }

        // ---- MMA phase: 4 ksteps ----
        uint32_t bbase = sb + SM_B + st * BSTG;
        #pragma unroll
        for (int ks = 0; ks < 4; ks++) {
            uint32_t kB = (uint32_t)ks * 32;
            uint32_t aP[2][4], aN[2][4];
            #pragma unroll
            for (int mt = 0; mt < 2; mt++) {
                uint32_t aoff = SWZ(aRowByte + mt * 2048u + kB + aKHalf);
                ldm_x4(sb + SM_AP + aoff, aP[mt]);
                ldm_x4(sb + SM_AN + aoff, aN[mt]);
            }
            #pragma unroll
            for (int pr = 0; pr < 2; pr++) {
                uint32_t boff = SWZ(bByte + (nbBase + 2 * pr) * 1024u + kB);
                uint32_t bh[4], bp[4], bn[4];
                ldm_x4(bbase + 0 * B_BYTES + boff, bh);
                ldm_x4(bbase + 1 * B_BYTES + boff, bp);
                ldm_x4(bbase + 2 * B_BYTES + boff, bn);
                mma16816(accP[0][2*pr],   aP[0], bh);
                mma16816(accP[1][2*pr],   aP[1], bh);
                mma16816(accP[0][2*pr+1], aP[0], bh + 2);
                mma16816(accP[1][2*pr+1], aP[1], bh + 2);
                mma16816(accN[0][2*pr],   aN[0], bh);
                mma16816(accN[1][2*pr],   aN[1], bh);
                mma16816(accN[0][2*pr+1], aN[0], bh + 2);
                mma16816(accN[1][2*pr+1], aN[1], bh + 2);
                mma16816(accP[0][2*pr],   aP[0], bp);
                mma16816(accP[1][2*pr],   aP[1], bp);
                mma16816(accP[0][2*pr+1], aP[0], bp + 2);
                mma16816(accP[1][2*pr+1], aP[1], bp + 2);
                mma16816(accN[0][2*pr],   aN[0], bn);
                mma16816(accN[1][2*pr],   aN[1], bn);
                mma16816(accN[0][2*pr+1], aN[0], bn + 2);
                mma16816(accN[1][2*pr+1], aN[1], bn + 2);
            }
            if (wn == 1) {     // block 8 (denominator col) via x2
                uint32_t boff = SWZ(bByteX2 + 8192u + kB);
                uint32_t bh2[2], bp2[2], bn2[2];
                ldm_x2(bbase + 0 * B_BYTES + boff, bh2);
                ldm_x2(bbase + 1 * B_BYTES + boff, bp2);
                ldm_x2(bbase + 2 * B_BYTES + boff, bn2);
                mma16816(accP[0][4], aP[0], bh2);
                mma16816(accP[1][4], aP[1], bh2);
                mma16816(accN[0][4], aN[0], bh2);
                mma16816(accN[1][4], aN[1], bh2);
                mma16816(accP[0][4], aP[0], bp2);
                mma16816(accP[1][4], aP[1], bp2);
                mma16816(accN[0][4], aN[0], bn2);
                mma16816(accN[1][4], aN[1], bn2);
            }
        }
    }

    // ---- epilogue: write fp32 partials ----
    int gp = lane >> 2, tg = lane & 3;
    int nBlk = 4 + wn;
    #pragma unroll
    for (int mt = 0; mt < 2; mt++) {
        int row0 = i0 + wm * 32 + mt * 16 + gp;
        for (int nb = 0; nb < nBlk; nb++) {
            int col = (nbBase + nb) * 8 + tg * 2;
            size_t o0 = (size_t)row0 * STRIDE_OUT + col;
            size_t o1 = (size_t)(row0 + 8) * STRIDE_OUT + col;
            g_numP[sp][o0]     = accP[mt][nb][0];
            g_numP[sp][o0 + 1] = accP[mt][nb][1];
            g_numP[sp][o1]     = accP[mt][nb][2];
            g_numP[sp][o1 + 1] = accP[mt][nb][3];
            g_numN[sp][o0]     = accN[mt][nb][0];
            g_numN[sp][o0 + 1] = accN[mt][nb][1];
            g_numN[sp][o1]     = accN[mt][nb][2];
            g_numN[sp][o1 + 1] = accN[mt][nb][3];
        }
    }
}

// ---------------- kernel 4: combine splits, scale, divide, ELU ----------------
__global__ void k_final(float* __restrict__ out) {
    int idx = blockIdx.x * 256 + threadIdx.x;
    int i = idx >> 6, c = idx & 63;
    size_t b = (size_t)i * STRIDE_OUT;
    float p = g_p[i], q = g_q[i];
    float nP = 0.f, nN = 0.f, dP = 0.f, dN = 0.f;
    #pragma unroll
    for (int s2 = 0; s2 < KSPLIT; s2++) {
        nP += g_numP[s2][b + c];  nN += g_numN[s2][b + c];
        dP += g_numP[s2][b + 64]; dN += g_numN[s2][b + 64];
    }
    float hv = (p * nP + q * nN) / (p * dP + q * dN);
    out[idx] = hv > 0.f ? hv : expm1f(hv);
}

extern "C" void kernel_launch(void* const* d_in, const int* in_sizes, int n_in,
                              void* d_out, int out_size) {
    const float* x   = (const float*)d_in[0];
    const int*   adj = (const int*)  d_in[1];
    const float* W   = (const float*)d_in[2];
    const float* a   = (const float*)d_in[3];
    float* out = (float*)d_out;

    cudaFuncSetAttribute(k_main_tc, cudaFuncAttributeMaxDynamicSharedMemorySize, SM_TOTAL);

    k_gemm_h<<<NN/64, 256>>>(x, W, a);
    dim3 gt(NN/256, NB);
    k_tables<<<gt, 256>>>();
    dim3 gm(NN/MT, KSPLIT);
    k_main_tc<<<gm, 256, SM_TOTAL>>>(adj);
    k_final<<<(NN*FO)/256, 256>>>(out);
}